// round 13
// baseline (speedup 1.0000x reference)
#include <cuda_runtime.h>
#include <cuda_fp16.h>
#include <math.h>
#include <stdint.h>

#define HDIM 2048
#define SLEN 2048
#define NH 16
#define NKV 8
#define HD 128
#define IDIM 8192
#define QKV_N 4096
#define WTOTAL 62914560

// weight region offsets (floats)
#define W_O    8388608
#define W_UP   12582912
#define W_GATE 29360128
#define W_DOWN 46137344

// ---------------- scratch (device globals; no allocation) ----------------
__device__ __half g_wh   [(size_t)WTOTAL];           // fp16 weights (mlp interleaved)
__device__ __half g_xh   [(size_t)SLEN * HDIM];      // normed activations (half)
__device__ __half g_qkvh [(size_t)SLEN * QKV_N];     // qkv half (rope in place)
__device__ __half g_attnh[(size_t)SLEN * HDIM];      // attention out (half)
__device__ float  g_hid  [(size_t)SLEN * HDIM];      // residual stream fp32
__device__ __half g_h1h  [(size_t)SLEN * IDIM];      // silu(gate)*up (half)

// ---------------- helpers ----------------
__device__ __forceinline__ uint32_t smem_to_u32(const void* p) {
    uint32_t a;
    asm("{ .reg .u64 t; cvta.to.shared.u64 t, %1; cvt.u32.u64 %0, t; }" : "=r"(a) : "l"(p));
    return a;
}
#define CP_ASYNC16(s, g) asm volatile("cp.async.cg.shared.global [%0], [%1], 16;" :: "r"(s), "l"(g))
#define CP_COMMIT() asm volatile("cp.async.commit_group;" ::: "memory")
#define CP_WAIT0() asm volatile("cp.async.wait_group 0;" ::: "memory")
#define CP_WAIT3() asm volatile("cp.async.wait_group 3;" ::: "memory")

#define LDSM_X4(r0, r1, r2, r3, addr) \
    asm volatile("ldmatrix.sync.aligned.m8n8.x4.shared.b16 {%0,%1,%2,%3}, [%4];" \
        : "=r"(r0), "=r"(r1), "=r"(r2), "=r"(r3) : "r"(addr))
#define LDSM_X4_T(r0, r1, r2, r3, addr) \
    asm volatile("ldmatrix.sync.aligned.m8n8.x4.trans.shared.b16 {%0,%1,%2,%3}, [%4];" \
        : "=r"(r0), "=r"(r1), "=r"(r2), "=r"(r3) : "r"(addr))

// mma.sync m16n8k16 fp16 -> fp32
__device__ __forceinline__ void mma_f16(float* d, const uint32_t* a, const uint32_t* b) {
    asm volatile(
        "mma.sync.aligned.m16n8k16.row.col.f32.f16.f16.f32 "
        "{%0,%1,%2,%3},{%4,%5,%6,%7},{%8,%9},{%0,%1,%2,%3};"
        : "+f"(d[0]), "+f"(d[1]), "+f"(d[2]), "+f"(d[3])
        : "r"(a[0]), "r"(a[1]), "r"(a[2]), "r"(a[3]), "r"(b[0]), "r"(b[1]));
}

// ---------------- dummy (keeps ncu capture window on gemm<1>) ----------------
__global__ void dummy_kernel() {}

// ---------------- fp16 mma GEMM NT: C[M,N] = A[M,K] @ B[N,K]^T ---------------
// MODE 0: fp32 out (+resid). MODE 1: half out. MODE 2: fused silu, half out N/2.
// BM=BN=128, BK=32, 256 threads (8 warps 2x4), warp tile 64x32, 5-stage pipe.
#define BM 128
#define BN 128
#define BK 32
#define NSTG 5
#define SAW 20                                // row stride in words (80B, 16B-aligned)
#define TILE_B (BM * SAW * 4)                 // 10240 bytes per tile
#define STAGE_B (2 * TILE_B)                  // 20480
#define GEMM_SMEM (NSTG * STAGE_B)            // 102400

__device__ __forceinline__ void load_tile(const __half* __restrict__ Ag,
                                          const __half* __restrict__ Bg, int K,
                                          uint32_t base, int stage, int tid, int k0) {
    uint32_t ab = base + stage * STAGE_B;
    uint32_t bb = ab + TILE_B;
    #pragma unroll
    for (int i = 0; i < 2; i++) {              // 128 rows x 4 chunks(16B) each tile
        int idx = tid + i * 256;
        int r = idx >> 2, c = idx & 3;
        uint32_t off = r * (SAW * 4) + c * 16;
        CP_ASYNC16(ab + off, Ag + (size_t)r * K + k0 + c * 8);
        CP_ASYNC16(bb + off, Bg + (size_t)r * K + k0 + c * 8);
    }
}

template <int MODE>
__global__ __launch_bounds__(256, 2)
void gemm_f16(const __half* __restrict__ A, const __half* __restrict__ B,
              const float* __restrict__ resid, void* __restrict__ Cv,
              int M, int N, int K) {
    extern __shared__ char smem[];
    uint32_t s0 = smem_to_u32(smem);
    int tid = threadIdx.x;
    int warp = tid >> 5, lane = tid & 31;
    int wm = warp >> 2, wn = warp & 3;
    int g = lane >> 2, tg = lane & 3;
    int bn = blockIdx.x, bm = blockIdx.y;

    const __half* Ag = A + (size_t)bm * BM * K;
    const __half* Bg = B + (size_t)bn * BN * K;
    int T = K / BK;

    uint32_t lr = lane & 7, quad = (uint32_t)lane >> 3;
    uint32_t woff = (quad >> 1) * 4;           // 16B chunk within kstep
    uint32_t aoffb[4], boffb[2];
    #pragma unroll
    for (int mi = 0; mi < 4; mi++)
        aoffb[mi] = ((wm * 64 + mi * 16 + (quad & 1) * 8 + lr) * SAW + woff) * 4;
    #pragma unroll
    for (int p = 0; p < 2; p++)
        boffb[p] = ((wn * 32 + p * 16 + (quad & 1) * 8 + lr) * SAW + woff) * 4;

    float acc[4][4][4];
    #pragma unroll
    for (int mi = 0; mi < 4; mi++)
        #pragma unroll
        for (int ni = 0; ni < 4; ni++)
            #pragma unroll
            for (int r = 0; r < 4; r++) acc[mi][ni][r] = 0.f;

    #pragma unroll
    for (int s = 0; s < NSTG - 1; s++) {       // prologue: 4 stages in flight
        load_tile(Ag, Bg, K, s0, s, tid, s * BK);
        CP_COMMIT();
    }

    for (int t = 0; t < T; t++) {
        CP_WAIT3();                            // stage t complete (<=3 pending)
        __syncthreads();
        int tn = t + (NSTG - 1);
        if (tn < T) load_tile(Ag, Bg, K, s0, tn % NSTG, tid, tn * BK);
        CP_COMMIT();                           // always commit: invariant 4 pending
        uint32_t abase = s0 + (t % NSTG) * STAGE_B;
        uint32_t bbase = abase + TILE_B;
        #pragma unroll
        for (int ks = 0; ks < 2; ks++) {
            uint32_t kb = ks * 32;             // 32B per kstep
            uint32_t a[4][4], b[4][2];
            #pragma unroll
            for (int mi = 0; mi < 4; mi++)
                LDSM_X4(a[mi][0], a[mi][1], a[mi][2], a[mi][3], abase + aoffb[mi] + kb);
            #pragma unroll
            for (int p = 0; p < 2; p++)
                LDSM_X4(b[2*p][0], b[2*p+1][0], b[2*p][1], b[2*p+1][1], bbase + boffb[p] + kb);
            #pragma unroll
            for (int mi = 0; mi < 4; mi++)
                #pragma unroll
                for (int ni = 0; ni < 4; ni++)
                    mma_f16(acc[mi][ni], a[mi], b[ni]);
        }
    }

    #pragma unroll
    for (int mi = 0; mi < 4; mi++) {
        int r0 = bm * BM + wm * 64 + mi * 16 + g;
        #pragma unroll
        for (int ni = 0; ni < 4; ni++) {
            int c = bn * BN + wn * 32 + ni * 8 + tg * 2;
            if (MODE == 2) {                    // fused silu: (up, gate) pair
                __half* C = (__half*)Cv;
                int NO = N >> 1;
                int j = c >> 1;
                float u0 = acc[mi][ni][0], g0 = acc[mi][ni][1];
                float u1 = acc[mi][ni][2], g1 = acc[mi][ni][3];
                float v0 = u0 * (g0 / (1.f + __expf(-g0)));
                float v1 = u1 * (g1 / (1.f + __expf(-g1)));
                C[(size_t)r0 * NO + j]       = __float2half_rn(v0);
                C[(size_t)(r0 + 8) * NO + j] = __float2half_rn(v1);
            } else if (MODE == 1) {
                __half* C = (__half*)Cv;
                size_t o0 = (size_t)r0 * N + c;
                size_t o1 = (size_t)(r0 + 8) * N + c;
                *(__half2*)(C + o0) = __floats2half2_rn(acc[mi][ni][0], acc[mi][ni][1]);
                *(__half2*)(C + o1) = __floats2half2_rn(acc[mi][ni][2], acc[mi][ni][3]);
            } else {
                float* C = (float*)Cv;
                size_t o0 = (size_t)r0 * N + c;
                size_t o1 = (size_t)(r0 + 8) * N + c;
                float2 v0 = make_float2(acc[mi][ni][0], acc[mi][ni][1]);
                float2 v1 = make_float2(acc[mi][ni][2], acc[mi][ni][3]);
                float2 q0 = *(const float2*)(resid + o0);
                float2 q1 = *(const float2*)(resid + o1);
                v0.x += q0.x; v0.y += q0.y;
                v1.x += q1.x; v1.y += q1.y;
                *(float2*)(C + o0) = v0;
                *(float2*)(C + o1) = v1;
            }
        }
    }
}

// ---------------- weights fp32 -> fp16 (mlp region row-interleaved) ----------
__global__ void wconv_kernel(const float* __restrict__ w, __half* __restrict__ o) {
    size_t i = (size_t)blockIdx.x * 256 + threadIdx.x;   // float4 index
    size_t f = i * 4;
    size_t src = f;
    if (f >= (size_t)W_UP && f < (size_t)W_DOWN) {
        size_t rel = f - W_UP;
        size_t r = rel >> 11, c = rel & 2047;
        src = ((r & 1) ? (size_t)W_GATE : (size_t)W_UP) + (r >> 1) * 2048 + c;
    }
    float4 v = *(const float4*)(w + src);
    __half2 h0 = __floats2half2_rn(v.x, v.y);
    __half2 h1 = __floats2half2_rn(v.z, v.w);
    ((uint2*)o)[i] = make_uint2(*(uint32_t*)&h0, *(uint32_t*)&h1);
}

// ---------------- RMSNorm (fp32 in, half out) ----------------
__global__ void rmsnorm_kernel(const float* __restrict__ x, const float* __restrict__ w,
                               __half* __restrict__ y) {
    int s = blockIdx.x;
    int tid = threadIdx.x;
    const float4* xr = (const float4*)(x + (size_t)s * HDIM);
    const float4* wr = (const float4*)w;
    float4 v0 = xr[tid];
    float4 v1 = xr[tid + 256];
    float ss = v0.x*v0.x + v0.y*v0.y + v0.z*v0.z + v0.w*v0.w
             + v1.x*v1.x + v1.y*v1.y + v1.z*v1.z + v1.w*v1.w;
    __shared__ float red[8];
    #pragma unroll
    for (int o = 16; o; o >>= 1) ss += __shfl_xor_sync(0xffffffffu, ss, o);
    if ((tid & 31) == 0) red[tid >> 5] = ss;
    __syncthreads();
    if (tid < 8) {
        float t = red[tid];
        #pragma unroll
        for (int o = 4; o; o >>= 1) t += __shfl_xor_sync(0xffu, t, o);
        if (tid == 0) red[0] = t;
    }
    __syncthreads();
    float inv = rsqrtf(red[0] * (1.0f / HDIM) + 1e-6f);
    float4 w0 = wr[tid], w1 = wr[tid + 256];
    uint2* yr = (uint2*)(y + (size_t)s * HDIM);
    __half2 a0 = __floats2half2_rn(v0.x*w0.x*inv, v0.y*w0.y*inv);
    __half2 a1 = __floats2half2_rn(v0.z*w0.z*inv, v0.w*w0.w*inv);
    __half2 b0 = __floats2half2_rn(v1.x*w1.x*inv, v1.y*w1.y*inv);
    __half2 b1 = __floats2half2_rn(v1.z*w1.z*inv, v1.w*w1.w*inv);
    yr[tid]       = make_uint2(*(uint32_t*)&a0, *(uint32_t*)&a1);
    yr[tid + 256] = make_uint2(*(uint32_t*)&b0, *(uint32_t*)&b1);
}

// ---------------- RoPE in place on half qkv (q+k heads) ----------------
__global__ void rope_kernel(__half* __restrict__ qkvh, const float* __restrict__ cs,
                            const float* __restrict__ sn) {
    int lane = threadIdx.x & 31;
    int w = threadIdx.x >> 5;
    int hh = blockIdx.y * 8 + w;
    int s = blockIdx.x;
    int base = (hh < NH) ? hh * HD : HDIM + (hh - NH) * HD;
    __half* p = qkvh + (size_t)s * QKV_N + base;
    int d = lane * 2;
    float2 c1 = *(const float2*)(cs + s * HD + d);
    float2 s1 = *(const float2*)(sn + s * HD + d);
    float2 c2 = *(const float2*)(cs + s * HD + d + 64);
    float2 s2 = *(const float2*)(sn + s * HD + d + 64);
    float2 x1 = __half22float2(*(__half2*)(p + d));
    float2 x2 = __half22float2(*(__half2*)(p + d + 64));
    *(__half2*)(p + d)      = __floats2half2_rn(x1.x * c1.x - x2.x * s1.x,
                                                x1.y * c1.y - x2.y * s1.y);
    *(__half2*)(p + d + 64) = __floats2half2_rn(x2.x * c2.x + x1.x * s2.x,
                                                x2.y * c2.y + x1.y * s2.y);
}

// ---------------- Flash attention: fp16 mma, cp.async double-buffered K/V,
//                  ldmatrix.trans for V, heavy-first schedule (round-8) ------
#define QSTRH 136
#define QSTRW 68
#define KVROWB (QSTRH * 2)                    // 272 bytes per 128-half row
#define KVTILE_B (64 * KVROWB)                // 17408 bytes per K or V tile
#define ATT_Q_B (128 * KVROWB)                // 34816
#define ATT_SMEM (ATT_Q_B + 4 * KVTILE_B)     // 104448 bytes

__global__ __launch_bounds__(256)
void attn_f16(const __half* __restrict__ qkvh, __half* __restrict__ outh) {
    extern __shared__ __half ash[];
    uint32_t qbase = smem_to_u32(ash);
    uint32_t kbase = qbase + ATT_Q_B;
    uint32_t vbase = kbase + 2 * KVTILE_B;

    int bid = blockIdx.x;
    int h = bid & 15;
    int p = bid >> 4;
    int qt = (p < 8) ? (15 - p) : (p - 8);   // heavy tiles first
    int tid = threadIdx.x;
    int warp = tid >> 5, lane = tid & 31;
    int g = lane >> 2, tg = lane & 3;
    int kvh = h >> 1;
    const float scale = 0.08838834764831845f;

    uint32_t lr = lane & 7, quad = (uint32_t)lane >> 3;
    uint32_t woff = (quad >> 1) * 4;
    uint32_t qoffb = ((warp * 16 + (quad & 1) * 8 + lr) * QSTRW + woff) * 4;
    uint32_t koffb[4];
    #pragma unroll
    for (int pp = 0; pp < 4; pp++)
        koffb[pp] = ((pp * 16 + (quad & 1) * 8 + lr) * QSTRW + woff) * 4;
    uint32_t voffb = ((quad & 1) * 8 + lr) * KVROWB + (quad >> 1) * 16;

    // load Q tile
    #pragma unroll
    for (int i = 0; i < 8; i++) {
        int idx = tid + i * 256;
        int r = idx >> 4, c = idx & 15;
        *(uint4*)((char*)ash + r * KVROWB + c * 16) =
            *(const uint4*)(qkvh + (size_t)(qt * 128 + r) * QKV_N + h * HD + c * 8);
    }

    const __half* ksrc = qkvh + HDIM + kvh * HD;
    const __half* vsrc = qkvh + HDIM + NKV * HD + kvh * HD;
    int nkt = 2 * qt + 2;

    {
        uint32_t kb = kbase, vb = vbase;
        #pragma unroll
        for (int i = 0; i < 4; i++) {
            int idx = tid + i * 256;
            int r = idx >> 4, c = idx & 15;
            uint32_t off = r * KVROWB + c * 16;
            CP_ASYNC16(kb + off, ksrc + (size_t)r * QKV_N + c * 8);
            CP_ASYNC16(vb + off, vsrc + (size_t)r * QKV_N + c * 8);
        }
        CP_COMMIT();
    }

    float o[16][4];
    #pragma unroll
    for (int nt = 0; nt < 16; nt++)
        #pragma unroll
        for (int r = 0; r < 4; r++) o[nt][r] = 0.f;
    float m0 = -INFINITY, m1 = -INFINITY, l0 = 0.f, l1 = 0.f;

    int row0 = qt * 128 + warp * 16 + g;
    int row1 = row0 + 8;

    for (int kt = 0; kt < nkt; kt++) {
        CP_WAIT0();
        __syncthreads();
        if (kt + 1 < nkt) {
            uint32_t kb = kbase + ((kt + 1) & 1) * KVTILE_B;
            uint32_t vb = vbase + ((kt + 1) & 1) * KVTILE_B;
            const __half* kr = ksrc + (size_t)(kt + 1) * 64 * QKV_N;
            const __half* vr = vsrc + (size_t)(kt + 1) * 64 * QKV_N;
            #pragma unroll
            for (int i = 0; i < 4; i++) {
                int idx = tid + i * 256;
                int r = idx >> 4, c = idx & 15;
                uint32_t off = r * KVROWB + c * 16;
                CP_ASYNC16(kb + off, kr + (size_t)r * QKV_N + c * 8);
                CP_ASYNC16(vb + off, vr + (size_t)r * QKV_N + c * 8);
            }
            CP_COMMIT();
        }
        uint32_t kcur = kbase + (kt & 1) * KVTILE_B;
        uint32_t vcur = vbase + (kt & 1) * KVTILE_B;

        float s[8][4];
        #pragma unroll
        for (int nt = 0; nt < 8; nt++)
            #pragma unroll
            for (int r = 0; r < 4; r++) s[nt][r] = 0.f;
        #pragma unroll
        for (int ks = 0; ks < 8; ks++) {
            uint32_t kb = ks * 32;
            uint32_t a[4], b[4][2];
            LDSM_X4(a[0], a[1], a[2], a[3], qbase + qoffb + kb);
            #pragma unroll
            for (int pp = 0; pp < 4; pp++) {
                uint32_t b0, b1, b2, b3;
                LDSM_X4(b0, b1, b2, b3, kcur + koffb[pp] + kb);
                b[0][0] = b0; b[1][0] = b1; b[0][1] = b2; b[1][1] = b3;
                mma_f16(s[2*pp],     a, b[0]);
                mma_f16(s[2*pp + 1], a, b[1]);
            }
        }

        bool diag = (kt >= 2 * qt);
        float tm0 = -INFINITY, tm1 = -INFINITY;
        #pragma unroll
        for (int nt = 0; nt < 8; nt++) {
            #pragma unroll
            for (int r = 0; r < 4; r++) s[nt][r] *= scale;
            if (diag) {
                int c0 = kt * 64 + nt * 8 + 2 * tg;
                if (c0 > row0)     s[nt][0] = -INFINITY;
                if (c0 + 1 > row0) s[nt][1] = -INFINITY;
                if (c0 > row1)     s[nt][2] = -INFINITY;
                if (c0 + 1 > row1) s[nt][3] = -INFINITY;
            }
            tm0 = fmaxf(tm0, fmaxf(s[nt][0], s[nt][1]));
            tm1 = fmaxf(tm1, fmaxf(s[nt][2], s[nt][3]));
        }
        tm0 = fmaxf(tm0, __shfl_xor_sync(0xffffffffu, tm0, 1));
        tm0 = fmaxf(tm0, __shfl_xor_sync(0xffffffffu, tm0, 2));
        tm1 = fmaxf(tm1, __shfl_xor_sync(0xffffffffu, tm1, 1));
        tm1 = fmaxf(tm1, __shfl_xor_sync(0xffffffffu, tm1, 2));
        float mn0 = fmaxf(m0, tm0), mn1 = fmaxf(m1, tm1);
        float corr0 = __expf(m0 - mn0), corr1 = __expf(m1 - mn1);

        uint32_t ph0[8], ph1[8];
        float ls0 = 0.f, ls1 = 0.f;
        #pragma unroll
        for (int nt = 0; nt < 8; nt++) {
            float p00 = __expf(s[nt][0] - mn0);
            float p01 = __expf(s[nt][1] - mn0);
            float p10 = __expf(s[nt][2] - mn1);
            float p11 = __expf(s[nt][3] - mn1);
            ls0 += p00 + p01; ls1 += p10 + p11;
            __half2 h0 = __floats2half2_rn(p00, p01);
            __half2 h1 = __floats2half2_rn(p10, p11);
            ph0[nt] = *(uint32_t*)&h0;
            ph1[nt] = *(uint32_t*)&h1;
        }
        ls0 += __shfl_xor_sync(0xffffffffu, ls0, 1);
        ls0 += __shfl_xor_sync(0xffffffffu, ls0, 2);
        ls1 += __shfl_xor_sync(0xffffffffu, ls1, 1);
        ls1 += __shfl_xor_sync(0xffffffffu, ls1, 2);
        l0 = l0 * corr0 + ls0;
        l1 = l1 * corr1 + ls1;
        m0 = mn0; m1 = mn1;
        #pragma unroll
        for (int nt = 0; nt < 16; nt++) {
            o[nt][0] *= corr0; o[nt][1] *= corr0;
            o[nt][2] *= corr1; o[nt][3] *= corr1;
        }

        #pragma unroll
        for (int ks = 0; ks < 4; ks++) {
            uint32_t a[4];
            a[0] = ph0[2 * ks];
            a[1] = ph1[2 * ks];
            a[2] = ph0[2 * ks + 1];
            a[3] = ph1[2 * ks + 1];
            uint32_t krow = ks * 16 * KVROWB;
            #pragma unroll
            for (int pp = 0; pp < 8; pp++) {
                uint32_t b0, b1, b2, b3;
                LDSM_X4_T(b0, b1, b2, b3, vcur + voffb + krow + pp * 32);
                uint32_t bb0[2] = {b0, b1}, bb1[2] = {b2, b3};
                mma_f16(o[2*pp],     a, bb0);
                mma_f16(o[2*pp + 1], a, bb1);
            }
        }
        __syncthreads();
    }

    float inv0 = 1.f / l0, inv1 = 1.f / l1;
    #pragma unroll
    for (int nt = 0; nt < 16; nt++) {
        int col = h * HD + nt * 8 + 2 * tg;
        __half2 w0 = __floats2half2_rn(o[nt][0] * inv0, o[nt][1] * inv0);
        __half2 w1 = __floats2half2_rn(o[nt][2] * inv1, o[nt][3] * inv1);
        *(__half2*)(outh + (size_t)row0 * HDIM + col) = w0;
        *(__half2*)(outh + (size_t)row1 * HDIM + col) = w1;
    }
}

// ---------------- launch ----------------
extern "C" void kernel_launch(void* const* d_in, const int* in_sizes, int n_in,
                              void* d_out, int out_size) {
    const float* hidden = (const float*)d_in[0];
    const float* wflat  = (const float*)d_in[1];
    const float* ln1    = (const float*)d_in[2];
    const float* ln2    = (const float*)d_in[3];
    const float* cosb   = (const float*)d_in[4];
    const float* sinb   = (const float*)d_in[5];
    float* out = (float*)d_out;

    __half *wh, *xh, *qkvh, *attnh, *h1h;
    float *hid;
    cudaGetSymbolAddress((void**)&wh,    g_wh);
    cudaGetSymbolAddress((void**)&xh,    g_xh);
    cudaGetSymbolAddress((void**)&qkvh,  g_qkvh);
    cudaGetSymbolAddress((void**)&attnh, g_attnh);
    cudaGetSymbolAddress((void**)&hid,   g_hid);
    cudaGetSymbolAddress((void**)&h1h,   g_h1h);

    cudaFuncSetAttribute(gemm_f16<0>, cudaFuncAttributeMaxDynamicSharedMemorySize, GEMM_SMEM);
    cudaFuncSetAttribute(gemm_f16<1>, cudaFuncAttributeMaxDynamicSharedMemorySize, GEMM_SMEM);
    cudaFuncSetAttribute(gemm_f16<2>, cudaFuncAttributeMaxDynamicSharedMemorySize, GEMM_SMEM);
    cudaFuncSetAttribute(attn_f16, cudaFuncAttributeMaxDynamicSharedMemorySize, ATT_SMEM);

    // -1) dummy: keeps ncu capture (in-call launch idx 3) on gemm_qkv
    dummy_kernel<<<1, 32>>>();
    // 0) weights fp32 -> fp16 (mlp rows interleaved)
    wconv_kernel<<<WTOTAL / 4 / 256, 256>>>(wflat, wh);
    // 1) input rmsnorm -> half
    rmsnorm_kernel<<<SLEN, 256>>>(hidden, ln1, xh);
    // 2) fused QKV projection -> half   <-- ncu capture target
    gemm_f16<1><<<dim3(QKV_N / BN, SLEN / BM), 256, GEMM_SMEM>>>(xh, wh, nullptr, qkvh,
                                                                 SLEN, QKV_N, HDIM);
    // 3) RoPE in place on half (q+k heads)
    rope_kernel<<<dim3(SLEN, 3), 256>>>(qkvh, cosb, sinb);
    // 4) causal attention (heavy-first schedule)
    attn_f16<<<256, 256, ATT_SMEM>>>(qkvh, attnh);
    // 5) o-projection + residual (fp32 out)
    gemm_f16<0><<<dim3(HDIM / BN, SLEN / BM), 256, GEMM_SMEM>>>(attnh, wh + W_O,
                                                                hidden, hid,
                                                                SLEN, HDIM, HDIM);
    // 6) post-attention rmsnorm -> half
    rmsnorm_kernel<<<SLEN, 256>>>(hid, ln2, xh);
    // 7) fused up|gate projection + silu -> h1 (half, N/2 out)
    gemm_f16<2><<<dim3(2 * IDIM / BN, SLEN / BM), 256, GEMM_SMEM>>>(xh, wh + W_UP,
                                                                    nullptr, h1h,
                                                                    SLEN, 2 * IDIM, HDIM);
    // 8) down projection + residual -> output (fp32)
    gemm_f16<0><<<dim3(HDIM / BN, SLEN / BM), 256, GEMM_SMEM>>>(h1h, wh + W_DOWN,
                                                                hid, out,
                                                                SLEN, HDIM, IDIM);
}

// round 14
// speedup vs baseline: 1.0799x; 1.0799x over previous
#include <cuda_runtime.h>
#include <cuda_fp16.h>
#include <math.h>
#include <stdint.h>

#define HDIM 2048
#define SLEN 2048
#define NH 16
#define NKV 8
#define HD 128
#define IDIM 8192
#define QKV_N 4096
#define WTOTAL 62914560

// weight region offsets (floats)
#define W_O    8388608
#define W_UP   12582912
#define W_GATE 29360128
#define W_DOWN 46137344

// ---------------- scratch (device globals; no allocation) ----------------
__device__ __half g_wh   [(size_t)WTOTAL];           // fp16 weights (mlp interleaved)
__device__ __half g_xh   [(size_t)SLEN * HDIM];      // normed activations (half)
__device__ __half g_qkvh [(size_t)SLEN * QKV_N];     // qkv half (rope in place)
__device__ __half g_attnh[(size_t)SLEN * HDIM];      // attention out (half)
__device__ float  g_hid  [(size_t)SLEN * HDIM];      // residual stream fp32
__device__ __half g_h1h  [(size_t)SLEN * IDIM];      // silu(gate)*up (half)

// ---------------- helpers ----------------
__device__ __forceinline__ uint32_t smem_to_u32(const void* p) {
    uint32_t a;
    asm("{ .reg .u64 t; cvta.to.shared.u64 t, %1; cvt.u32.u64 %0, t; }" : "=r"(a) : "l"(p));
    return a;
}
#define CP_ASYNC16(s, g) asm volatile("cp.async.cg.shared.global [%0], [%1], 16;" :: "r"(s), "l"(g))
#define CP_COMMIT() asm volatile("cp.async.commit_group;" ::: "memory")
#define CP_WAIT0() asm volatile("cp.async.wait_group 0;" ::: "memory")
#define CP_WAIT1() asm volatile("cp.async.wait_group 1;" ::: "memory")

#define LDSM_X4(r0, r1, r2, r3, addr) \
    asm volatile("ldmatrix.sync.aligned.m8n8.x4.shared.b16 {%0,%1,%2,%3}, [%4];" \
        : "=r"(r0), "=r"(r1), "=r"(r2), "=r"(r3) : "r"(addr))
#define LDSM_X4_T(r0, r1, r2, r3, addr) \
    asm volatile("ldmatrix.sync.aligned.m8n8.x4.trans.shared.b16 {%0,%1,%2,%3}, [%4];" \
        : "=r"(r0), "=r"(r1), "=r"(r2), "=r"(r3) : "r"(addr))

// mma.sync m16n8k16 fp16 -> fp32
__device__ __forceinline__ void mma_f16(float* d, const uint32_t* a, const uint32_t* b) {
    asm volatile(
        "mma.sync.aligned.m16n8k16.row.col.f32.f16.f16.f32 "
        "{%0,%1,%2,%3},{%4,%5,%6,%7},{%8,%9},{%0,%1,%2,%3};"
        : "+f"(d[0]), "+f"(d[1]), "+f"(d[2]), "+f"(d[3])
        : "r"(a[0]), "r"(a[1]), "r"(a[2]), "r"(a[3]), "r"(b[0]), "r"(b[1]));
}

// ---------------- fp16 mma GEMM NT: C[M,N] = A[M,K] @ B[N,K]^T ---------------
// MODE 0: fp32 out (+resid). MODE 1: half out. MODE 2: fused silu, half out N/2.
// BM=BN=128, BK=64, 256 threads (8 warps 2x4), warp tile 64x32, 3-stage (round-8).
#define BM 128
#define BN 128
#define BK 64
#define SAW 36                                // smem row stride in 32-bit words
#define TILE_B (BM * SAW * 4)                 // 18432 bytes per tile
#define STAGE_B (2 * TILE_B)
#define GEMM_SMEM (3 * STAGE_B)               // 110592

__device__ __forceinline__ void load_tile(const __half* __restrict__ Ag,
                                          const __half* __restrict__ Bg, int K,
                                          uint32_t base, int stage, int tid, int k0) {
    uint32_t ab = base + stage * STAGE_B;
    uint32_t bb = ab + TILE_B;
    #pragma unroll
    for (int i = 0; i < 4; i++) {
        int idx = tid + i * 256;
        int r = idx >> 3, c = idx & 7;
        uint32_t off = r * (SAW * 4) + c * 16;
        CP_ASYNC16(ab + off, Ag + (size_t)r * K + k0 + c * 8);
        CP_ASYNC16(bb + off, Bg + (size_t)r * K + k0 + c * 8);
    }
}

template <int MODE>
__global__ __launch_bounds__(256, 2)
void gemm_f16(const __half* __restrict__ A, const __half* __restrict__ B,
              const float* __restrict__ resid, void* __restrict__ Cv,
              int M, int N, int K) {
    extern __shared__ char smem[];
    uint32_t s0 = smem_to_u32(smem);
    int tid = threadIdx.x;
    int warp = tid >> 5, lane = tid & 31;
    int wm = warp >> 2, wn = warp & 3;
    int g = lane >> 2, tg = lane & 3;
    int bn = blockIdx.x, bm = blockIdx.y;

    const __half* Ag = A + (size_t)bm * BM * K;
    const __half* Bg = B + (size_t)bn * BN * K;
    int T = K / BK;

    uint32_t lr = lane & 7, quad = (uint32_t)lane >> 3;
    uint32_t woff = (quad >> 1) * 4;
    uint32_t aoffb[4], boffb[2];
    #pragma unroll
    for (int mi = 0; mi < 4; mi++)
        aoffb[mi] = ((wm * 64 + mi * 16 + (quad & 1) * 8 + lr) * SAW + woff) * 4;
    #pragma unroll
    for (int p = 0; p < 2; p++)
        boffb[p] = ((wn * 32 + p * 16 + (quad & 1) * 8 + lr) * SAW + woff) * 4;

    float acc[4][4][4];
    #pragma unroll
    for (int mi = 0; mi < 4; mi++)
        #pragma unroll
        for (int ni = 0; ni < 4; ni++)
            #pragma unroll
            for (int r = 0; r < 4; r++) acc[mi][ni][r] = 0.f;

    load_tile(Ag, Bg, K, s0, 0, tid, 0);
    CP_COMMIT();
    load_tile(Ag, Bg, K, s0, 1, tid, BK);
    CP_COMMIT();

    for (int t = 0; t < T; t++) {
        CP_WAIT1();
        __syncthreads();
        int tn = t + 2;
        if (tn < T) load_tile(Ag, Bg, K, s0, tn % 3, tid, tn * BK);
        CP_COMMIT();
        uint32_t abase = s0 + (t % 3) * STAGE_B;
        uint32_t bbase = abase + TILE_B;
        #pragma unroll
        for (int ks = 0; ks < 4; ks++) {
            uint32_t kb = ks * 32;
            uint32_t a[4][4], b[4][2];
            #pragma unroll
            for (int mi = 0; mi < 4; mi++)
                LDSM_X4(a[mi][0], a[mi][1], a[mi][2], a[mi][3], abase + aoffb[mi] + kb);
            #pragma unroll
            for (int p = 0; p < 2; p++)
                LDSM_X4(b[2*p][0], b[2*p+1][0], b[2*p][1], b[2*p+1][1], bbase + boffb[p] + kb);
            #pragma unroll
            for (int mi = 0; mi < 4; mi++)
                #pragma unroll
                for (int ni = 0; ni < 4; ni++)
                    mma_f16(acc[mi][ni], a[mi], b[ni]);
        }
    }

    #pragma unroll
    for (int mi = 0; mi < 4; mi++) {
        int r0 = bm * BM + wm * 64 + mi * 16 + g;
        #pragma unroll
        for (int ni = 0; ni < 4; ni++) {
            int c = bn * BN + wn * 32 + ni * 8 + tg * 2;
            if (MODE == 2) {                    // fused silu: (up, gate) pair
                __half* C = (__half*)Cv;
                int NO = N >> 1;
                int j = c >> 1;
                float u0 = acc[mi][ni][0], g0 = acc[mi][ni][1];
                float u1 = acc[mi][ni][2], g1 = acc[mi][ni][3];
                float v0 = u0 * (g0 / (1.f + __expf(-g0)));
                float v1 = u1 * (g1 / (1.f + __expf(-g1)));
                C[(size_t)r0 * NO + j]       = __float2half_rn(v0);
                C[(size_t)(r0 + 8) * NO + j] = __float2half_rn(v1);
            } else if (MODE == 1) {
                __half* C = (__half*)Cv;
                size_t o0 = (size_t)r0 * N + c;
                size_t o1 = (size_t)(r0 + 8) * N + c;
                *(__half2*)(C + o0) = __floats2half2_rn(acc[mi][ni][0], acc[mi][ni][1]);
                *(__half2*)(C + o1) = __floats2half2_rn(acc[mi][ni][2], acc[mi][ni][3]);
            } else {
                float* C = (float*)Cv;
                size_t o0 = (size_t)r0 * N + c;
                size_t o1 = (size_t)(r0 + 8) * N + c;
                float2 v0 = make_float2(acc[mi][ni][0], acc[mi][ni][1]);
                float2 v1 = make_float2(acc[mi][ni][2], acc[mi][ni][3]);
                float2 q0 = *(const float2*)(resid + o0);
                float2 q1 = *(const float2*)(resid + o1);
                v0.x += q0.x; v0.y += q0.y;
                v1.x += q1.x; v1.y += q1.y;
                *(float2*)(C + o0) = v0;
                *(float2*)(C + o1) = v1;
            }
        }
    }
}

// ---------------- prep: wconv (fp32->fp16, mlp interleaved) + rmsnorm1 -------
// blocks [0, WCONV_BLKS): weight conversion; blocks [WCONV_BLKS, +SLEN): rmsnorm.
#define WCONV_BLKS (WTOTAL / 4 / 256)          // 61440

__device__ __forceinline__ void rmsnorm_body(const float* __restrict__ x,
                                             const float* __restrict__ w,
                                             __half* __restrict__ y, int s, int tid) {
    const float4* xr = (const float4*)(x + (size_t)s * HDIM);
    const float4* wr = (const float4*)w;
    float4 v0 = xr[tid];
    float4 v1 = xr[tid + 256];
    float ss = v0.x*v0.x + v0.y*v0.y + v0.z*v0.z + v0.w*v0.w
             + v1.x*v1.x + v1.y*v1.y + v1.z*v1.z + v1.w*v1.w;
    __shared__ float red[8];
    #pragma unroll
    for (int o = 16; o; o >>= 1) ss += __shfl_xor_sync(0xffffffffu, ss, o);
    if ((tid & 31) == 0) red[tid >> 5] = ss;
    __syncthreads();
    if (tid < 8) {
        float t = red[tid];
        #pragma unroll
        for (int o = 4; o; o >>= 1) t += __shfl_xor_sync(0xffu, t, o);
        if (tid == 0) red[0] = t;
    }
    __syncthreads();
    float inv = rsqrtf(red[0] * (1.0f / HDIM) + 1e-6f);
    float4 w0 = wr[tid], w1 = wr[tid + 256];
    uint2* yr = (uint2*)(y + (size_t)s * HDIM);
    __half2 a0 = __floats2half2_rn(v0.x*w0.x*inv, v0.y*w0.y*inv);
    __half2 a1 = __floats2half2_rn(v0.z*w0.z*inv, v0.w*w0.w*inv);
    __half2 b0 = __floats2half2_rn(v1.x*w1.x*inv, v1.y*w1.y*inv);
    __half2 b1 = __floats2half2_rn(v1.z*w1.z*inv, v1.w*w1.w*inv);
    yr[tid]       = make_uint2(*(uint32_t*)&a0, *(uint32_t*)&a1);
    yr[tid + 256] = make_uint2(*(uint32_t*)&b0, *(uint32_t*)&b1);
}

__global__ void prep_kernel(const float* __restrict__ w, __half* __restrict__ o,
                            const float* __restrict__ hidden,
                            const float* __restrict__ ln1, __half* __restrict__ xh) {
    int b = blockIdx.x;
    if (b < WCONV_BLKS) {
        size_t i = (size_t)b * 256 + threadIdx.x;
        size_t f = i * 4;
        size_t src = f;
        if (f >= (size_t)W_UP && f < (size_t)W_DOWN) {
            size_t rel = f - W_UP;
            size_t r = rel >> 11, c = rel & 2047;
            src = ((r & 1) ? (size_t)W_GATE : (size_t)W_UP) + (r >> 1) * 2048 + c;
        }
        float4 v = *(const float4*)(w + src);
        __half2 h0 = __floats2half2_rn(v.x, v.y);
        __half2 h1 = __floats2half2_rn(v.z, v.w);
        ((uint2*)o)[i] = make_uint2(*(uint32_t*)&h0, *(uint32_t*)&h1);
    } else {
        rmsnorm_body(hidden, ln1, xh, b - WCONV_BLKS, threadIdx.x);
    }
}

// ---------------- RMSNorm standalone (post-attn) ----------------
__global__ void rmsnorm_kernel(const float* __restrict__ x, const float* __restrict__ w,
                               __half* __restrict__ y) {
    rmsnorm_body(x, w, y, blockIdx.x, threadIdx.x);
}

// ---------------- RoPE in place on half qkv (q+k heads) ----------------
__global__ void rope_kernel(__half* __restrict__ qkvh, const float* __restrict__ cs,
                            const float* __restrict__ sn) {
    int lane = threadIdx.x & 31;
    int w = threadIdx.x >> 5;
    int hh = blockIdx.y * 8 + w;
    int s = blockIdx.x;
    int base = (hh < NH) ? hh * HD : HDIM + (hh - NH) * HD;
    __half* p = qkvh + (size_t)s * QKV_N + base;
    int d = lane * 2;
    float2 c1 = *(const float2*)(cs + s * HD + d);
    float2 s1 = *(const float2*)(sn + s * HD + d);
    float2 c2 = *(const float2*)(cs + s * HD + d + 64);
    float2 s2 = *(const float2*)(sn + s * HD + d + 64);
    float2 x1 = __half22float2(*(__half2*)(p + d));
    float2 x2 = __half22float2(*(__half2*)(p + d + 64));
    *(__half2*)(p + d)      = __floats2half2_rn(x1.x * c1.x - x2.x * s1.x,
                                                x1.y * c1.y - x2.y * s1.y);
    *(__half2*)(p + d + 64) = __floats2half2_rn(x2.x * c2.x + x1.x * s2.x,
                                                x2.y * c2.y + x1.y * s2.y);
}

// ---------------- Flash attention: fp16 mma (round-8 config) -----------------
#define QSTRH 136
#define QSTRW 68
#define KVROWB (QSTRH * 2)                    // 272 bytes per 128-half row
#define KVTILE_B (64 * KVROWB)                // 17408 bytes per K or V tile
#define ATT_Q_B (128 * KVROWB)                // 34816
#define ATT_SMEM (ATT_Q_B + 4 * KVTILE_B)     // 104448 bytes

__global__ __launch_bounds__(256)
void attn_f16(const __half* __restrict__ qkvh, __half* __restrict__ outh) {
    extern __shared__ __half ash[];
    uint32_t qbase = smem_to_u32(ash);
    uint32_t kbase = qbase + ATT_Q_B;
    uint32_t vbase = kbase + 2 * KVTILE_B;

    int bid = blockIdx.x;
    int h = bid & 15;
    int p = bid >> 4;
    int qt = (p < 8) ? (15 - p) : (p - 8);   // heavy tiles first
    int tid = threadIdx.x;
    int warp = tid >> 5, lane = tid & 31;
    int g = lane >> 2, tg = lane & 3;
    int kvh = h >> 1;
    const float scale = 0.08838834764831845f;

    uint32_t lr = lane & 7, quad = (uint32_t)lane >> 3;
    uint32_t woff = (quad >> 1) * 4;
    uint32_t qoffb = ((warp * 16 + (quad & 1) * 8 + lr) * QSTRW + woff) * 4;
    uint32_t koffb[4];
    #pragma unroll
    for (int pp = 0; pp < 4; pp++)
        koffb[pp] = ((pp * 16 + (quad & 1) * 8 + lr) * QSTRW + woff) * 4;
    uint32_t voffb = ((quad & 1) * 8 + lr) * KVROWB + (quad >> 1) * 16;

    // load Q tile
    #pragma unroll
    for (int i = 0; i < 8; i++) {
        int idx = tid + i * 256;
        int r = idx >> 4, c = idx & 15;
        *(uint4*)((char*)ash + r * KVROWB + c * 16) =
            *(const uint4*)(qkvh + (size_t)(qt * 128 + r) * QKV_N + h * HD + c * 8);
    }

    const __half* ksrc = qkvh + HDIM + kvh * HD;
    const __half* vsrc = qkvh + HDIM + NKV * HD + kvh * HD;
    int nkt = 2 * qt + 2;

    {
        uint32_t kb = kbase, vb = vbase;
        #pragma unroll
        for (int i = 0; i < 4; i++) {
            int idx = tid + i * 256;
            int r = idx >> 4, c = idx & 15;
            uint32_t off = r * KVROWB + c * 16;
            CP_ASYNC16(kb + off, ksrc + (size_t)r * QKV_N + c * 8);
            CP_ASYNC16(vb + off, vsrc + (size_t)r * QKV_N + c * 8);
        }
        CP_COMMIT();
    }

    float o[16][4];
    #pragma unroll
    for (int nt = 0; nt < 16; nt++)
        #pragma unroll
        for (int r = 0; r < 4; r++) o[nt][r] = 0.f;
    float m0 = -INFINITY, m1 = -INFINITY, l0 = 0.f, l1 = 0.f;

    int row0 = qt * 128 + warp * 16 + g;
    int row1 = row0 + 8;

    for (int kt = 0; kt < nkt; kt++) {
        CP_WAIT0();
        __syncthreads();
        if (kt + 1 < nkt) {
            uint32_t kb = kbase + ((kt + 1) & 1) * KVTILE_B;
            uint32_t vb = vbase + ((kt + 1) & 1) * KVTILE_B;
            const __half* kr = ksrc + (size_t)(kt + 1) * 64 * QKV_N;
            const __half* vr = vsrc + (size_t)(kt + 1) * 64 * QKV_N;
            #pragma unroll
            for (int i = 0; i < 4; i++) {
                int idx = tid + i * 256;
                int r = idx >> 4, c = idx & 15;
                uint32_t off = r * KVROWB + c * 16;
                CP_ASYNC16(kb + off, kr + (size_t)r * QKV_N + c * 8);
                CP_ASYNC16(vb + off, vr + (size_t)r * QKV_N + c * 8);
            }
            CP_COMMIT();
        }
        uint32_t kcur = kbase + (kt & 1) * KVTILE_B;
        uint32_t vcur = vbase + (kt & 1) * KVTILE_B;

        float s[8][4];
        #pragma unroll
        for (int nt = 0; nt < 8; nt++)
            #pragma unroll
            for (int r = 0; r < 4; r++) s[nt][r] = 0.f;
        #pragma unroll
        for (int ks = 0; ks < 8; ks++) {
            uint32_t kb = ks * 32;
            uint32_t a[4], b[4][2];
            LDSM_X4(a[0], a[1], a[2], a[3], qbase + qoffb + kb);
            #pragma unroll
            for (int pp = 0; pp < 4; pp++) {
                uint32_t b0, b1, b2, b3;
                LDSM_X4(b0, b1, b2, b3, kcur + koffb[pp] + kb);
                b[0][0] = b0; b[1][0] = b1; b[0][1] = b2; b[1][1] = b3;
                mma_f16(s[2*pp],     a, b[0]);
                mma_f16(s[2*pp + 1], a, b[1]);
            }
        }

        bool diag = (kt >= 2 * qt);
        float tm0 = -INFINITY, tm1 = -INFINITY;
        #pragma unroll
        for (int nt = 0; nt < 8; nt++) {
            #pragma unroll
            for (int r = 0; r < 4; r++) s[nt][r] *= scale;
            if (diag) {
                int c0 = kt * 64 + nt * 8 + 2 * tg;
                if (c0 > row0)     s[nt][0] = -INFINITY;
                if (c0 + 1 > row0) s[nt][1] = -INFINITY;
                if (c0 > row1)     s[nt][2] = -INFINITY;
                if (c0 + 1 > row1) s[nt][3] = -INFINITY;
            }
            tm0 = fmaxf(tm0, fmaxf(s[nt][0], s[nt][1]));
            tm1 = fmaxf(tm1, fmaxf(s[nt][2], s[nt][3]));
        }
        tm0 = fmaxf(tm0, __shfl_xor_sync(0xffffffffu, tm0, 1));
        tm0 = fmaxf(tm0, __shfl_xor_sync(0xffffffffu, tm0, 2));
        tm1 = fmaxf(tm1, __shfl_xor_sync(0xffffffffu, tm1, 1));
        tm1 = fmaxf(tm1, __shfl_xor_sync(0xffffffffu, tm1, 2));
        float mn0 = fmaxf(m0, tm0), mn1 = fmaxf(m1, tm1);
        float corr0 = __expf(m0 - mn0), corr1 = __expf(m1 - mn1);

        uint32_t ph0[8], ph1[8];
        float ls0 = 0.f, ls1 = 0.f;
        #pragma unroll
        for (int nt = 0; nt < 8; nt++) {
            float p00 = __expf(s[nt][0] - mn0);
            float p01 = __expf(s[nt][1] - mn0);
            float p10 = __expf(s[nt][2] - mn1);
            float p11 = __expf(s[nt][3] - mn1);
            ls0 += p00 + p01; ls1 += p10 + p11;
            __half2 h0 = __floats2half2_rn(p00, p01);
            __half2 h1 = __floats2half2_rn(p10, p11);
            ph0[nt] = *(uint32_t*)&h0;
            ph1[nt] = *(uint32_t*)&h1;
        }
        ls0 += __shfl_xor_sync(0xffffffffu, ls0, 1);
        ls0 += __shfl_xor_sync(0xffffffffu, ls0, 2);
        ls1 += __shfl_xor_sync(0xffffffffu, ls1, 1);
        ls1 += __shfl_xor_sync(0xffffffffu, ls1, 2);
        l0 = l0 * corr0 + ls0;
        l1 = l1 * corr1 + ls1;
        m0 = mn0; m1 = mn1;
        #pragma unroll
        for (int nt = 0; nt < 16; nt++) {
            o[nt][0] *= corr0; o[nt][1] *= corr0;
            o[nt][2] *= corr1; o[nt][3] *= corr1;
        }

        #pragma unroll
        for (int ks = 0; ks < 4; ks++) {
            uint32_t a[4];
            a[0] = ph0[2 * ks];
            a[1] = ph1[2 * ks];
            a[2] = ph0[2 * ks + 1];
            a[3] = ph1[2 * ks + 1];
            uint32_t krow = ks * 16 * KVROWB;
            #pragma unroll
            for (int pp = 0; pp < 8; pp++) {
                uint32_t b0, b1, b2, b3;
                LDSM_X4_T(b0, b1, b2, b3, vcur + voffb + krow + pp * 32);
                uint32_t bb0[2] = {b0, b1}, bb1[2] = {b2, b3};
                mma_f16(o[2*pp],     a, bb0);
                mma_f16(o[2*pp + 1], a, bb1);
            }
        }
        __syncthreads();
    }

    float inv0 = 1.f / l0, inv1 = 1.f / l1;
    #pragma unroll
    for (int nt = 0; nt < 16; nt++) {
        int col = h * HD + nt * 8 + 2 * tg;
        __half2 w0 = __floats2half2_rn(o[nt][0] * inv0, o[nt][1] * inv0);
        __half2 w1 = __floats2half2_rn(o[nt][2] * inv1, o[nt][3] * inv1);
        *(__half2*)(outh + (size_t)row0 * HDIM + col) = w0;
        *(__half2*)(outh + (size_t)row1 * HDIM + col) = w1;
    }
}

// ---------------- launch ----------------
extern "C" void kernel_launch(void* const* d_in, const int* in_sizes, int n_in,
                              void* d_out, int out_size) {
    const float* hidden = (const float*)d_in[0];
    const float* wflat  = (const float*)d_in[1];
    const float* ln1    = (const float*)d_in[2];
    const float* ln2    = (const float*)d_in[3];
    const float* cosb   = (const float*)d_in[4];
    const float* sinb   = (const float*)d_in[5];
    float* out = (float*)d_out;

    __half *wh, *xh, *qkvh, *attnh, *h1h;
    float *hid;
    cudaGetSymbolAddress((void**)&wh,    g_wh);
    cudaGetSymbolAddress((void**)&xh,    g_xh);
    cudaGetSymbolAddress((void**)&qkvh,  g_qkvh);
    cudaGetSymbolAddress((void**)&attnh, g_attnh);
    cudaGetSymbolAddress((void**)&hid,   g_hid);
    cudaGetSymbolAddress((void**)&h1h,   g_h1h);

    cudaFuncSetAttribute(gemm_f16<0>, cudaFuncAttributeMaxDynamicSharedMemorySize, GEMM_SMEM);
    cudaFuncSetAttribute(gemm_f16<1>, cudaFuncAttributeMaxDynamicSharedMemorySize, GEMM_SMEM);
    cudaFuncSetAttribute(gemm_f16<2>, cudaFuncAttributeMaxDynamicSharedMemorySize, GEMM_SMEM);
    cudaFuncSetAttribute(attn_f16, cudaFuncAttributeMaxDynamicSharedMemorySize, ATT_SMEM);

    // 0) prep: weights fp32->fp16 (mlp interleaved) + input rmsnorm
    prep_kernel<<<WCONV_BLKS + SLEN, 256>>>(wflat, wh, hidden, ln1, xh);
    // 1) fused QKV projection -> half
    gemm_f16<1><<<dim3(QKV_N / BN, SLEN / BM), 256, GEMM_SMEM>>>(xh, wh, nullptr, qkvh,
                                                                 SLEN, QKV_N, HDIM);
    // 2) RoPE in place on half (q+k heads)
    rope_kernel<<<dim3(SLEN, 3), 256>>>(qkvh, cosb, sinb);
    // 3) causal attention   <-- ncu capture target (4th launch)
    attn_f16<<<256, 256, ATT_SMEM>>>(qkvh, attnh);
    // 4) o-projection + residual (fp32 out)
    gemm_f16<0><<<dim3(HDIM / BN, SLEN / BM), 256, GEMM_SMEM>>>(attnh, wh + W_O,
                                                                hidden, hid,
                                                                SLEN, HDIM, HDIM);
    // 5) post-attention rmsnorm -> half
    rmsnorm_kernel<<<SLEN, 256>>>(hid, ln2, xh);
    // 6) fused up|gate projection + silu -> h1 (half, N/2 out)
    gemm_f16<2><<<dim3(2 * IDIM / BN, SLEN / BM), 256, GEMM_SMEM>>>(xh, wh + W_UP,
                                                                    nullptr, h1h,
                                                                    SLEN, 2 * IDIM, HDIM);
    // 7) down projection + residual -> output (fp32)
    gemm_f16<0><<<dim3(HDIM / BN, SLEN / BM), 256, GEMM_SMEM>>>(h1h, wh + W_DOWN,
                                                                hid, out,
                                                                SLEN, HDIM, IDIM);
}